// round 2
// baseline (speedup 1.0000x reference)
#include <cuda_runtime.h>
#include <math.h>
#include <stdint.h>

#define B_   256
#define T_   256
#define INSZ 512
#define HD   1024
#define NBLK 128
#define NTHR 128

// Ping-pong hidden state [2][B][4][HD] and inter-stack pred buffers [2][B][INSZ]
__device__ float g_h[2][B_ * 4 * HD];
__device__ float g_pred[2][B_ * INSZ];

// Grid barrier state (sense-reversing; self-resetting count)
__device__ unsigned g_count;
__device__ volatile unsigned g_sense;

__device__ __forceinline__ void grid_barrier(unsigned& ls)
{
    __syncthreads();
    if (threadIdx.x == 0) {
        unsigned s = ls ^ 1u;
        __threadfence();
        if (atomicAdd(&g_count, 1u) == NBLK - 1) {
            g_count = 0;
            __threadfence();
            g_sense = s;            // release
        } else {
            while (g_sense != s) { __nanosleep(32); }
        }
        __threadfence();            // acquire
        ls = s;
    }
    __syncthreads();
}

// ---------------------------------------------------------------------------
// 3-gate GEMM accumulate: 64j x 32b tile, 128 threads, 4x4 microtile.
// A loads bypass L1 (__ldcg) because A may be written by other SMs this launch.
// ---------------------------------------------------------------------------
__device__ __forceinline__ void accum3(
    const float* __restrict__ A, int astride,
    const float* __restrict__ W, int K, int nk,
    float (&accu)[4][4], float (&accr)[4][4], float (&accn)[4][4],
    int tx, int ty, int tid,
    float (&As)[32][36], float (&Wus)[32][68],
    float (&Wrs)[32][68], float (&Wns)[32][68])
{
    for (int k0 = 0; k0 < nk; k0 += 32) {
        __syncthreads();
#pragma unroll
        for (int i = 0; i < 2; i++) {
            int lin = tid + i * 128;
            int bb = lin >> 3, kq = lin & 7;
            float4 v = __ldcg((const float4*)(A + (size_t)bb * astride + (k0 + kq * 4)));
            As[kq * 4 + 0][bb] = v.x; As[kq * 4 + 1][bb] = v.y;
            As[kq * 4 + 2][bb] = v.z; As[kq * 4 + 3][bb] = v.w;
        }
#pragma unroll
        for (int i = 0; i < 4; i++) {
            int lin = tid + i * 128;
            int jj = lin >> 3, kq = lin & 7;
            size_t ro = (size_t)jj * K + (k0 + kq * 4);
            float4 vu = *(const float4*)(W + ro);
            float4 vr = *(const float4*)(W + (size_t)HD * K + ro);
            float4 vn = *(const float4*)(W + (size_t)(2 * HD) * K + ro);
            Wus[kq * 4 + 0][jj] = vu.x; Wus[kq * 4 + 1][jj] = vu.y;
            Wus[kq * 4 + 2][jj] = vu.z; Wus[kq * 4 + 3][jj] = vu.w;
            Wrs[kq * 4 + 0][jj] = vr.x; Wrs[kq * 4 + 1][jj] = vr.y;
            Wrs[kq * 4 + 2][jj] = vr.z; Wrs[kq * 4 + 3][jj] = vr.w;
            Wns[kq * 4 + 0][jj] = vn.x; Wns[kq * 4 + 1][jj] = vn.y;
            Wns[kq * 4 + 2][jj] = vn.z; Wns[kq * 4 + 3][jj] = vn.w;
        }
        __syncthreads();
#pragma unroll
        for (int kk = 0; kk < 32; kk++) {
            float4 a4 = *(const float4*)&As[kk][ty * 4];
            float4 u4 = *(const float4*)&Wus[kk][tx * 4];
            float4 r4 = *(const float4*)&Wrs[kk][tx * 4];
            float4 n4 = *(const float4*)&Wns[kk][tx * 4];
            float aa[4] = {a4.x, a4.y, a4.z, a4.w};
            float uu[4] = {u4.x, u4.y, u4.z, u4.w};
            float rr[4] = {r4.x, r4.y, r4.z, r4.w};
            float nn[4] = {n4.x, n4.y, n4.z, n4.w};
#pragma unroll
            for (int i = 0; i < 4; i++)
#pragma unroll
                for (int j = 0; j < 4; j++) {
                    accu[i][j] += aa[i] * uu[j];
                    accr[i][j] += aa[i] * rr[j];
                    accn[i][j] += aa[i] * nn[j];
                }
        }
    }
}

// Single-matrix accumulate: 32o x 32b tile, 128 threads, 2x4 microtile.
__device__ __forceinline__ void accum1(
    const float* __restrict__ A, int astride,
    const float* __restrict__ W, int wstride, int nk,
    float (&acc)[2][4],
    int tx, int ty, int tid,
    float (&As)[32][36], float (&Ws)[32][36])
{
    for (int k0 = 0; k0 < nk; k0 += 32) {
        __syncthreads();
#pragma unroll
        for (int i = 0; i < 2; i++) {
            int lin = tid + i * 128;
            int bb = lin >> 3, kq = lin & 7;
            float4 v = __ldcg((const float4*)(A + (size_t)bb * astride + (k0 + kq * 4)));
            As[kq * 4 + 0][bb] = v.x; As[kq * 4 + 1][bb] = v.y;
            As[kq * 4 + 2][bb] = v.z; As[kq * 4 + 3][bb] = v.w;
        }
#pragma unroll
        for (int i = 0; i < 2; i++) {
            int lin = tid + i * 128;
            int jj = lin >> 3, kq = lin & 7;
            float4 v = *(const float4*)(W + (size_t)jj * wstride + (k0 + kq * 4));
            Ws[kq * 4 + 0][jj] = v.x; Ws[kq * 4 + 1][jj] = v.y;
            Ws[kq * 4 + 2][jj] = v.z; Ws[kq * 4 + 3][jj] = v.w;
        }
        __syncthreads();
#pragma unroll
        for (int kk = 0; kk < 32; kk++) {
            float2 a2 = *(const float2*)&As[kk][ty * 2];
            float4 w4 = *(const float4*)&Ws[kk][tx * 4];
            float aa[2] = {a2.x, a2.y};
            float ww[4] = {w4.x, w4.y, w4.z, w4.w};
#pragma unroll
            for (int i = 0; i < 2; i++)
#pragma unroll
                for (int j = 0; j < 4; j++)
                    acc[i][j] += aa[i] * ww[j];
        }
    }
}

// ---------------------------------------------------------------------------
// One persistent kernel: the entire SGRU sequence + log_softmax + h copy-out.
// grid = 128 blocks (all co-resident), 128 threads.
// ---------------------------------------------------------------------------
__global__ void __launch_bounds__(NTHR) sgru_kernel(
    const float* __restrict__ xb, const float* __restrict__ h0,
    const float* __restrict__ Wx, const float* __restrict__ bx,
    const float* __restrict__ Wh, const float* __restrict__ bh,
    const float* __restrict__ Wo, const float* __restrict__ bo,
    float* __restrict__ out)
{
    __shared__ __align__(16) float As[32][36];
    __shared__ __align__(16) float Wus[32][68];
    __shared__ __align__(16) float Wrs[32][68];
    __shared__ __align__(16) float Wns[32][68];
    float (&Ws1)[32][36] = *(float (*)[32][36])&Wus[0][0];

    int tid = threadIdx.x;
    int bid = blockIdx.x;
    unsigned ls = g_sense;   // read before any block can flip it

    // ---- init: h0 -> g_h[0] ----
    {
        int g = bid * NTHR + tid;
        const float4* s4 = (const float4*)h0;
        float4* d4 = (float4*)g_h[0];
#pragma unroll 1
        for (int i = g; i < B_ * 4 * HD / 4; i += NBLK * NTHR) d4[i] = s4[i];
    }
    grid_barrier(ls);

#pragma unroll 1
    for (int t = 0; t < T_; t++) {
        int rd = t & 1, wr = rd ^ 1;
#pragma unroll 1
        for (int s = 0; s < 4; s++) {
            int wi = (s == 3) ? 2 : s;   // faithful to the source bug

            const float* x;
            int xstride;
            if (s == 0) { x = xb + (size_t)t * INSZ; xstride = T_ * INSZ; }
            else        { x = g_pred[(s - 1) & 1];   xstride = INSZ; }

            // ===== gate phase: 16 j-tiles x 8 b-tiles =====
            {
                int tx = tid & 15, ty = tid >> 4;
                int j0 = (bid & 15) * 64;
                int b0 = (bid >> 4) * 32;
                const float* Wxp = Wx + (size_t)wi * 3 * HD * INSZ + (size_t)j0 * INSZ;
                const float* Whp = Wh + (size_t)wi * 3 * HD * HD + (size_t)j0 * HD;
                const float* bx3 = bx + wi * 3 * HD;
                const float* bh3 = bh + wi * 3 * HD;
                const float* hrd = g_h[rd] + s * HD;
                float* hwr = g_h[wr] + s * HD;

                float accu[4][4], accr[4][4], accxn[4][4], acchn[4][4];
#pragma unroll
                for (int jj = 0; jj < 4; jj++) {
                    int jg = j0 + tx * 4 + jj;
                    float bu = bx3[jg] + bh3[jg];
                    float br = bx3[HD + jg] + bh3[HD + jg];
                    float bxn = bx3[2 * HD + jg];
                    float bhn = bh3[2 * HD + jg];
#pragma unroll
                    for (int i = 0; i < 4; i++) {
                        accu[i][jj] = bu; accr[i][jj] = br;
                        accxn[i][jj] = bxn; acchn[i][jj] = bhn;
                    }
                }
                accum3(x + (size_t)b0 * xstride, xstride, Wxp, INSZ, INSZ,
                       accu, accr, accxn, tx, ty, tid, As, Wus, Wrs, Wns);
                accum3(hrd + (size_t)b0 * (4 * HD), 4 * HD, Whp, HD, HD,
                       accu, accr, acchn, tx, ty, tid, As, Wus, Wrs, Wns);
#pragma unroll
                for (int i = 0; i < 4; i++) {
                    int b = b0 + ty * 4 + i;
                    int jg = j0 + tx * 4;
                    float4 hold = __ldcg((const float4*)(hrd + (size_t)b * (4 * HD) + jg));
                    float ho[4] = {hold.x, hold.y, hold.z, hold.w};
                    float4 hv;
                    float* hvp = &hv.x;
#pragma unroll
                    for (int jj = 0; jj < 4; jj++) {
                        float u = 1.0f / (1.0f + expf(-accu[i][jj]));
                        float r = 1.0f / (1.0f + expf(-accr[i][jj]));
                        float n = tanhf(accxn[i][jj] + r * acchn[i][jj]);
                        hvp[jj] = u * ho[jj] + (1.0f - u) * n;
                    }
                    *(float4*)(hwr + (size_t)b * (4 * HD) + jg) = hv;
                }
            }
            grid_barrier(ls);

            // ===== pred phase: 16 o-tiles x 8 b-tiles, 32x32 =====
            {
                int tx = tid & 7, ty = tid >> 3;
                int o0 = (bid & 15) * 32;
                int b0 = (bid >> 4) * 32;
                const float* Wop = Wo + (size_t)wi * INSZ * (HD + INSZ) + (size_t)o0 * (HD + INSZ);
                const float* bop = bo + wi * INSZ;
                const float* hn = g_h[wr] + s * HD;

                float acc[2][4];
#pragma unroll
                for (int jj = 0; jj < 4; jj++) {
                    float bv = bop[o0 + tx * 4 + jj];
                    acc[0][jj] = bv; acc[1][jj] = bv;
                }
                accum1(x + (size_t)b0 * xstride, xstride,
                       Wop, HD + INSZ, INSZ, acc, tx, ty, tid, As, Ws1);
                accum1(hn + (size_t)b0 * (4 * HD), 4 * HD,
                       Wop + INSZ, HD + INSZ, HD, acc, tx, ty, tid, As, Ws1);

                float* outp; int ostr;
                if (s == 3) { outp = out + (size_t)t * INSZ; ostr = T_ * INSZ; }
                else        { outp = g_pred[s & 1];          ostr = INSZ; }
#pragma unroll
                for (int i = 0; i < 2; i++) {
                    int b = b0 + ty * 2 + i;
                    float4 v = make_float4(acc[i][0], acc[i][1], acc[i][2], acc[i][3]);
                    *(float4*)(outp + (size_t)b * ostr + (o0 + tx * 4)) = v;
                }
            }
            grid_barrier(ls);
        }
    }

    // ---- copy final h (in g_h[0]) to out tail ----
    {
        int g = bid * NTHR + tid;
        const float4* s4 = (const float4*)g_h[0];
        float4* d4 = (float4*)(out + (size_t)B_ * T_ * INSZ);
#pragma unroll 1
        for (int i = g; i < B_ * 4 * HD / 4; i += NBLK * NTHR) d4[i] = __ldcg(s4 + i);
    }

    // ---- log_softmax over each 512-wide pred row ----
    {
        int w = tid >> 5, ln = tid & 31;
        int gw = bid * 4 + w;
#pragma unroll 1
        for (int r = gw; r < B_ * T_; r += NBLK * 4) {
            float* p = out + (size_t)r * INSZ;
            float v[16];
            float m = -1e30f;
#pragma unroll
            for (int i = 0; i < 16; i++) {
                v[i] = __ldcg(p + ln + i * 32);
                m = fmaxf(m, v[i]);
            }
#pragma unroll
            for (int off = 16; off > 0; off >>= 1)
                m = fmaxf(m, __shfl_xor_sync(0xffffffffu, m, off));
            float sm = 0.0f;
#pragma unroll
            for (int i = 0; i < 16; i++) sm += expf(v[i] - m);
#pragma unroll
            for (int off = 16; off > 0; off >>= 1)
                sm += __shfl_xor_sync(0xffffffffu, sm, off);
            float lsv = m + logf(sm);
#pragma unroll
            for (int i = 0; i < 16; i++) p[ln + i * 32] = v[i] - lsv;
        }
    }
}

// ---------------------------------------------------------------------------
extern "C" void kernel_launch(void* const* d_in, const int* in_sizes, int n_in,
                              void* d_out, int out_size)
{
    const float* xb = (const float*)d_in[0];
    const float* h0 = (const float*)d_in[1];
    const float* Wx = (const float*)d_in[2];
    const float* bx = (const float*)d_in[3];
    const float* Wh = (const float*)d_in[4];
    const float* bh = (const float*)d_in[5];
    const float* Wo = (const float*)d_in[6];
    const float* bo = (const float*)d_in[7];
    float* out = (float*)d_out;

    sgru_kernel<<<NBLK, NTHR>>>(xb, h0, Wx, bx, Wh, bh, Wo, bo, out);
}

// round 3
// speedup vs baseline: 1.2750x; 1.2750x over previous
#include <cuda_runtime.h>
#include <math.h>
#include <stdint.h>

#define B_   256
#define T_   256
#define INSZ 512
#define HD   1024
#define NBLK 128
#define NTHR 256

typedef unsigned long long u64;

// Ping-pong hidden state [2][B][4][HD] and inter-stack pred buffers [2][B][INSZ]
__device__ float g_h[2][B_ * 4 * HD];
__device__ float g_pred[2][B_ * INSZ];

// Grid barrier state (sense-reversing; self-resetting count)
__device__ unsigned g_count;
__device__ volatile unsigned g_sense;

__device__ __forceinline__ void grid_barrier(unsigned& ls)
{
    __syncthreads();
    if (threadIdx.x == 0) {
        unsigned s = ls ^ 1u;
        __threadfence();
        if (atomicAdd(&g_count, 1u) == NBLK - 1) {
            g_count = 0;
            __threadfence();
            g_sense = s;            // release
        } else {
            while (g_sense != s) { __nanosleep(32); }
        }
        __threadfence();            // acquire
        ls = s;
    }
    __syncthreads();
}

// ---- packed f32x2 helpers (sm_103a FFMA2 path) ----
__device__ __forceinline__ u64 pack2(float lo, float hi)
{
    u64 r;
    asm("mov.b64 %0, {%1, %2};" : "=l"(r) : "f"(lo), "f"(hi));
    return r;
}
__device__ __forceinline__ void unpack2(u64 v, float& lo, float& hi)
{
    asm("mov.b64 {%0, %1}, %2;" : "=f"(lo), "=f"(hi) : "l"(v));
}
__device__ __forceinline__ void ffma2(u64& d, u64 a, u64 b)
{
    asm("fma.rn.f32x2 %0, %1, %2, %0;" : "+l"(d) : "l"(a), "l"(b));
}

// ---------------------------------------------------------------------------
// 3-gate GEMM accumulate: 64j x 32b tile, 256 threads, microtile 4j x 2b.
// Accumulators are f32x2 pairs over adjacent j: acc[set][jpair][b].
// Register-prefetch pipeline over 32-wide k chunks.
// ---------------------------------------------------------------------------
__device__ __forceinline__ void accum3(
    const float* __restrict__ A, int astride,
    const float* __restrict__ W, int K, int nk,
    u64 (&au)[2][2], u64 (&ar)[2][2], u64 (&an)[2][2],
    int tx, int ty, int tid,
    float (&As)[32][36], float (&Wus)[32][68],
    float (&Wrs)[32][68], float (&Wns)[32][68])
{
    const int abb = tid >> 3, akq = tid & 7;       // A loader coords
    float4 pa;
    float4 pu[2], pr[2], pn[2];

    // prologue: prefetch chunk 0
    pa = __ldcg((const float4*)(A + (size_t)abb * astride + akq * 4));
#pragma unroll
    for (int i = 0; i < 2; i++) {
        int lin = tid + i * 256;
        int jj = lin >> 3, kq = lin & 7;
        size_t ro = (size_t)jj * K + kq * 4;
        pu[i] = *(const float4*)(W + ro);
        pr[i] = *(const float4*)(W + (size_t)HD * K + ro);
        pn[i] = *(const float4*)(W + (size_t)(2 * HD) * K + ro);
    }

    for (int k0 = 0; k0 < nk; k0 += 32) {
        __syncthreads();
        // store prefetched regs to smem (transposed [k][...])
        As[akq * 4 + 0][abb] = pa.x; As[akq * 4 + 1][abb] = pa.y;
        As[akq * 4 + 2][abb] = pa.z; As[akq * 4 + 3][abb] = pa.w;
#pragma unroll
        for (int i = 0; i < 2; i++) {
            int lin = tid + i * 256;
            int jj = lin >> 3, kq = lin & 7;
            Wus[kq * 4 + 0][jj] = pu[i].x; Wus[kq * 4 + 1][jj] = pu[i].y;
            Wus[kq * 4 + 2][jj] = pu[i].z; Wus[kq * 4 + 3][jj] = pu[i].w;
            Wrs[kq * 4 + 0][jj] = pr[i].x; Wrs[kq * 4 + 1][jj] = pr[i].y;
            Wrs[kq * 4 + 2][jj] = pr[i].z; Wrs[kq * 4 + 3][jj] = pr[i].w;
            Wns[kq * 4 + 0][jj] = pn[i].x; Wns[kq * 4 + 1][jj] = pn[i].y;
            Wns[kq * 4 + 2][jj] = pn[i].z; Wns[kq * 4 + 3][jj] = pn[i].w;
        }
        __syncthreads();
        // prefetch next chunk while computing this one
        int kn = k0 + 32;
        if (kn < nk) {
            pa = __ldcg((const float4*)(A + (size_t)abb * astride + (kn + akq * 4)));
#pragma unroll
            for (int i = 0; i < 2; i++) {
                int lin = tid + i * 256;
                int jj = lin >> 3, kq = lin & 7;
                size_t ro = (size_t)jj * K + (kn + kq * 4);
                pu[i] = *(const float4*)(W + ro);
                pr[i] = *(const float4*)(W + (size_t)HD * K + ro);
                pn[i] = *(const float4*)(W + (size_t)(2 * HD) * K + ro);
            }
        }
#pragma unroll
        for (int kk = 0; kk < 32; kk++) {
            float2 a2 = *(const float2*)&As[kk][ty * 2];
            u64 A0 = pack2(a2.x, a2.x);
            u64 A1 = pack2(a2.y, a2.y);
            ulonglong2 wu = *(const ulonglong2*)&Wus[kk][tx * 4];
            ulonglong2 wr = *(const ulonglong2*)&Wrs[kk][tx * 4];
            ulonglong2 wn = *(const ulonglong2*)&Wns[kk][tx * 4];
            ffma2(au[0][0], A0, wu.x); ffma2(au[1][0], A0, wu.y);
            ffma2(au[0][1], A1, wu.x); ffma2(au[1][1], A1, wu.y);
            ffma2(ar[0][0], A0, wr.x); ffma2(ar[1][0], A0, wr.y);
            ffma2(ar[0][1], A1, wr.x); ffma2(ar[1][1], A1, wr.y);
            ffma2(an[0][0], A0, wn.x); ffma2(an[1][0], A0, wn.y);
            ffma2(an[0][1], A1, wn.x); ffma2(an[1][1], A1, wn.y);
        }
    }
}

// Single-matrix accumulate: 32o x 32b tile, 256 threads, microtile 4o x 1b.
__device__ __forceinline__ void accum1(
    const float* __restrict__ A, int astride,
    const float* __restrict__ W, int wstride, int nk,
    u64 (&acc)[2],
    int tx, int ty, int tid,
    float (&As)[32][36], float (&Ws)[32][36])
{
    const int abb = tid >> 3, akq = tid & 7;
    const int wjj = tid >> 3, wkq = tid & 7;
    float4 pa, pw;

    pa = __ldcg((const float4*)(A + (size_t)abb * astride + akq * 4));
    pw = *(const float4*)(W + (size_t)wjj * wstride + wkq * 4);

    for (int k0 = 0; k0 < nk; k0 += 32) {
        __syncthreads();
        As[akq * 4 + 0][abb] = pa.x; As[akq * 4 + 1][abb] = pa.y;
        As[akq * 4 + 2][abb] = pa.z; As[akq * 4 + 3][abb] = pa.w;
        Ws[wkq * 4 + 0][wjj] = pw.x; Ws[wkq * 4 + 1][wjj] = pw.y;
        Ws[wkq * 4 + 2][wjj] = pw.z; Ws[wkq * 4 + 3][wjj] = pw.w;
        __syncthreads();
        int kn = k0 + 32;
        if (kn < nk) {
            pa = __ldcg((const float4*)(A + (size_t)abb * astride + (kn + akq * 4)));
            pw = *(const float4*)(W + (size_t)wjj * wstride + (kn + wkq * 4));
        }
#pragma unroll
        for (int kk = 0; kk < 32; kk++) {
            float a = As[kk][ty];
            u64 A0 = pack2(a, a);
            ulonglong2 w = *(const ulonglong2*)&Ws[kk][tx * 4];
            ffma2(acc[0], A0, w.x);
            ffma2(acc[1], A0, w.y);
        }
    }
}

// ---------------------------------------------------------------------------
// One persistent kernel: entire SGRU sequence + log_softmax + h copy-out.
// grid = 128 blocks, 256 threads.
// ---------------------------------------------------------------------------
__global__ void __launch_bounds__(NTHR) sgru_kernel(
    const float* __restrict__ xb, const float* __restrict__ h0,
    const float* __restrict__ Wx, const float* __restrict__ bx,
    const float* __restrict__ Wh, const float* __restrict__ bh,
    const float* __restrict__ Wo, const float* __restrict__ bo,
    float* __restrict__ out)
{
    __shared__ __align__(16) float As[32][36];
    __shared__ __align__(16) float Wus[32][68];
    __shared__ __align__(16) float Wrs[32][68];
    __shared__ __align__(16) float Wns[32][68];
    float (&Ws1)[32][36] = *(float (*)[32][36])&Wus[0][0];

    int tid = threadIdx.x;
    int bid = blockIdx.x;
    unsigned ls = g_sense;   // read before any block can flip it

    // ---- init: h0 -> g_h[0] ----
    {
        int g = bid * NTHR + tid;
        const float4* s4 = (const float4*)h0;
        float4* d4 = (float4*)g_h[0];
#pragma unroll 1
        for (int i = g; i < B_ * 4 * HD / 4; i += NBLK * NTHR) d4[i] = s4[i];
    }
    grid_barrier(ls);

#pragma unroll 1
    for (int t = 0; t < T_; t++) {
        int rd = t & 1, wr = rd ^ 1;
#pragma unroll 1
        for (int s = 0; s < 4; s++) {
            int wi = (s == 3) ? 2 : s;   // faithful to the source bug

            const float* x;
            int xstride;
            if (s == 0) { x = xb + (size_t)t * INSZ; xstride = T_ * INSZ; }
            else        { x = g_pred[(s - 1) & 1];   xstride = INSZ; }

            // ===== gate phase: 16 j-tiles (64) x 8 b-tiles (32) =====
            {
                int tx = tid & 15, ty = tid >> 4;     // tx: 16 x 4j, ty: 16 x 2b
                int j0 = (bid & 15) * 64;
                int b0 = (bid >> 4) * 32;
                const float* Wxp = Wx + (size_t)wi * 3 * HD * INSZ + (size_t)j0 * INSZ;
                const float* Whp = Wh + (size_t)wi * 3 * HD * HD + (size_t)j0 * HD;
                const float* bx3 = bx + wi * 3 * HD;
                const float* bh3 = bh + wi * 3 * HD;
                const float* hrd = g_h[rd] + s * HD;
                float* hwr = g_h[wr] + s * HD;

                u64 au[2][2], ar[2][2], axn[2][2], ahn[2][2];
#pragma unroll
                for (int p = 0; p < 2; p++) {
                    int jg = j0 + tx * 4 + p * 2;
                    u64 bu = pack2(bx3[jg] + bh3[jg], bx3[jg + 1] + bh3[jg + 1]);
                    u64 br = pack2(bx3[HD + jg] + bh3[HD + jg],
                                   bx3[HD + jg + 1] + bh3[HD + jg + 1]);
                    u64 bxn = pack2(bx3[2 * HD + jg], bx3[2 * HD + jg + 1]);
                    u64 bhn = pack2(bh3[2 * HD + jg], bh3[2 * HD + jg + 1]);
#pragma unroll
                    for (int i = 0; i < 2; i++) {
                        au[p][i] = bu; ar[p][i] = br;
                        axn[p][i] = bxn; ahn[p][i] = bhn;
                    }
                }
                accum3(x + (size_t)b0 * xstride, xstride, Wxp, INSZ, INSZ,
                       au, ar, axn, tx, ty, tid, As, Wus, Wrs, Wns);
                accum3(hrd + (size_t)b0 * (4 * HD), 4 * HD, Whp, HD, HD,
                       au, ar, ahn, tx, ty, tid, As, Wus, Wrs, Wns);

#pragma unroll
                for (int i = 0; i < 2; i++) {
                    int b = b0 + ty * 2 + i;
                    int jg = j0 + tx * 4;
                    float4 hold = __ldcg((const float4*)(hrd + (size_t)b * (4 * HD) + jg));
                    float ho[4] = {hold.x, hold.y, hold.z, hold.w};
                    float uv[4], rv[4], xnv[4], hnv[4];
#pragma unroll
                    for (int p = 0; p < 2; p++) {
                        unpack2(au[p][i], uv[p * 2], uv[p * 2 + 1]);
                        unpack2(ar[p][i], rv[p * 2], rv[p * 2 + 1]);
                        unpack2(axn[p][i], xnv[p * 2], xnv[p * 2 + 1]);
                        unpack2(ahn[p][i], hnv[p * 2], hnv[p * 2 + 1]);
                    }
                    float4 hv;
                    float* hvp = &hv.x;
#pragma unroll
                    for (int jj = 0; jj < 4; jj++) {
                        float u = 1.0f / (1.0f + expf(-uv[jj]));
                        float r = 1.0f / (1.0f + expf(-rv[jj]));
                        float n = tanhf(xnv[jj] + r * hnv[jj]);
                        hvp[jj] = u * ho[jj] + (1.0f - u) * n;
                    }
                    *(float4*)(hwr + (size_t)b * (4 * HD) + jg) = hv;
                }
            }
            grid_barrier(ls);

            // ===== pred phase: 16 o-tiles (32) x 8 b-tiles (32) =====
            {
                int tx = tid & 7, ty = tid >> 3;      // tx: 8 x 4o, ty: 32 x 1b
                int o0 = (bid & 15) * 32;
                int b0 = (bid >> 4) * 32;
                const float* Wop = Wo + (size_t)wi * INSZ * (HD + INSZ) + (size_t)o0 * (HD + INSZ);
                const float* bop = bo + wi * INSZ;
                const float* hn = g_h[wr] + s * HD;

                u64 acc[2];
                acc[0] = pack2(bop[o0 + tx * 4], bop[o0 + tx * 4 + 1]);
                acc[1] = pack2(bop[o0 + tx * 4 + 2], bop[o0 + tx * 4 + 3]);

                accum1(x + (size_t)b0 * xstride, xstride,
                       Wop, HD + INSZ, INSZ, acc, tx, ty, tid, As, Ws1);
                accum1(hn + (size_t)b0 * (4 * HD), 4 * HD,
                       Wop + INSZ, HD + INSZ, HD, acc, tx, ty, tid, As, Ws1);

                float* outp; int ostr;
                if (s == 3) { outp = out + (size_t)t * INSZ; ostr = T_ * INSZ; }
                else        { outp = g_pred[s & 1];          ostr = INSZ; }
                int b = b0 + ty;
                float4 v;
                unpack2(acc[0], v.x, v.y);
                unpack2(acc[1], v.z, v.w);
                *(float4*)(outp + (size_t)b * ostr + (o0 + tx * 4)) = v;
            }
            grid_barrier(ls);
        }
    }

    // ---- copy final h (in g_h[0]) to out tail ----
    {
        int g = bid * NTHR + tid;
        const float4* s4 = (const float4*)g_h[0];
        float4* d4 = (float4*)(out + (size_t)B_ * T_ * INSZ);
#pragma unroll 1
        for (int i = g; i < B_ * 4 * HD / 4; i += NBLK * NTHR) d4[i] = __ldcg(s4 + i);
    }

    // ---- log_softmax over each 512-wide pred row ----
    {
        int w = tid >> 5, ln = tid & 31;      // 8 warps per block
        int gw = bid * 8 + w;
#pragma unroll 1
        for (int r = gw; r < B_ * T_; r += NBLK * 8) {
            float* p = out + (size_t)r * INSZ;
            float v[16];
            float m = -1e30f;
#pragma unroll
            for (int i = 0; i < 16; i++) {
                v[i] = __ldcg(p + ln + i * 32);
                m = fmaxf(m, v[i]);
            }
#pragma unroll
            for (int off = 16; off > 0; off >>= 1)
                m = fmaxf(m, __shfl_xor_sync(0xffffffffu, m, off));
            float sm = 0.0f;
#pragma unroll
            for (int i = 0; i < 16; i++) sm += expf(v[i] - m);
#pragma unroll
            for (int off = 16; off > 0; off >>= 1)
                sm += __shfl_xor_sync(0xffffffffu, sm, off);
            float lsv = m + logf(sm);
#pragma unroll
            for (int i = 0; i < 16; i++) p[ln + i * 32] = v[i] - lsv;
        }
    }
}

// ---------------------------------------------------------------------------
extern "C" void kernel_launch(void* const* d_in, const int* in_sizes, int n_in,
                              void* d_out, int out_size)
{
    const float* xb = (const float*)d_in[0];
    const float* h0 = (const float*)d_in[1];
    const float* Wx = (const float*)d_in[2];
    const float* bx = (const float*)d_in[3];
    const float* Wh = (const float*)d_in[4];
    const float* bh = (const float*)d_in[5];
    const float* Wo = (const float*)d_in[6];
    const float* bo = (const float*)d_in[7];
    float* out = (float*)d_out;

    sgru_kernel<<<NBLK, NTHR>>>(xb, h0, Wx, bx, Wh, bh, Wo, bo, out);
}

// round 4
// speedup vs baseline: 1.4383x; 1.1281x over previous
#include <cuda_runtime.h>
#include <math.h>
#include <stdint.h>

#define B_   256
#define T_   256
#define INSZ 512
#define HD   1024
#define NBLK 128
#define NTHR 128

typedef unsigned long long u64;

// Ping-pong hidden state [2][B][4][HD] and inter-stack pred buffers [2][B][INSZ]
__device__ float g_h[2][B_ * 4 * HD];
__device__ float g_pred[2][B_ * INSZ];

// Grid barrier state (sense-reversing; self-resetting count)
__device__ unsigned g_count;
__device__ volatile unsigned g_sense;

__device__ __forceinline__ void grid_barrier(unsigned& ls)
{
    __syncthreads();
    if (threadIdx.x == 0) {
        unsigned s = ls ^ 1u;
        __threadfence();
        if (atomicAdd(&g_count, 1u) == NBLK - 1) {
            g_count = 0;
            __threadfence();
            g_sense = s;            // release
        } else {
            while (g_sense != s) { __nanosleep(32); }
        }
        __threadfence();            // acquire
        ls = s;
    }
    __syncthreads();
}

// ---- packed f32x2 helpers (sm_103a FFMA2 path) ----
__device__ __forceinline__ u64 pack2(float lo, float hi)
{
    u64 r;
    asm("mov.b64 %0, {%1, %2};" : "=l"(r) : "f"(lo), "f"(hi));
    return r;
}
__device__ __forceinline__ void unpack2(u64 v, float& lo, float& hi)
{
    asm("mov.b64 {%0, %1}, %2;" : "=f"(lo), "=f"(hi) : "l"(v));
}
__device__ __forceinline__ void ffma2(u64& d, u64 a, u64 b)
{
    asm("fma.rn.f32x2 %0, %1, %2, %0;" : "+l"(d) : "l"(a), "l"(b));
}

// ---------------------------------------------------------------------------
// 3-gate GEMM accumulate: 32j x 64b tile, 128 threads, microtile 4j x 4b.
// Accumulators: f32x2 pairs over adjacent j: acc[gate][jpair][b].
// Register-prefetch pipeline over 32-wide k chunks.
// ---------------------------------------------------------------------------
__device__ __forceinline__ void accum3(
    const float* __restrict__ A, int astride,
    const float* __restrict__ W, int K, int nk,
    u64 (&au)[2][4], u64 (&ar)[2][4], u64 (&an)[2][4],
    int tx, int ty, int tid,
    float (&As)[32][68], float (&Wus)[32][36],
    float (&Wrs)[32][36], float (&Wns)[32][36])
{
    float4 pa[4];
    float4 pu[2], pr[2], pn[2];

    // prologue: prefetch chunk 0
#pragma unroll
    for (int i = 0; i < 4; i++) {
        int lin = tid + i * 128;
        int bb = lin >> 3, kq = lin & 7;
        pa[i] = __ldcg((const float4*)(A + (size_t)bb * astride + kq * 4));
    }
#pragma unroll
    for (int i = 0; i < 2; i++) {
        int lin = tid + i * 128;
        int jj = lin >> 3, kq = lin & 7;
        size_t ro = (size_t)jj * K + kq * 4;
        pu[i] = *(const float4*)(W + ro);
        pr[i] = *(const float4*)(W + (size_t)HD * K + ro);
        pn[i] = *(const float4*)(W + (size_t)(2 * HD) * K + ro);
    }

    for (int k0 = 0; k0 < nk; k0 += 32) {
        __syncthreads();
        // store prefetched regs to smem (transposed [k][...])
#pragma unroll
        for (int i = 0; i < 4; i++) {
            int lin = tid + i * 128;
            int bb = lin >> 3, kq = lin & 7;
            As[kq * 4 + 0][bb] = pa[i].x; As[kq * 4 + 1][bb] = pa[i].y;
            As[kq * 4 + 2][bb] = pa[i].z; As[kq * 4 + 3][bb] = pa[i].w;
        }
#pragma unroll
        for (int i = 0; i < 2; i++) {
            int lin = tid + i * 128;
            int jj = lin >> 3, kq = lin & 7;
            Wus[kq * 4 + 0][jj] = pu[i].x; Wus[kq * 4 + 1][jj] = pu[i].y;
            Wus[kq * 4 + 2][jj] = pu[i].z; Wus[kq * 4 + 3][jj] = pu[i].w;
            Wrs[kq * 4 + 0][jj] = pr[i].x; Wrs[kq * 4 + 1][jj] = pr[i].y;
            Wrs[kq * 4 + 2][jj] = pr[i].z; Wrs[kq * 4 + 3][jj] = pr[i].w;
            Wns[kq * 4 + 0][jj] = pn[i].x; Wns[kq * 4 + 1][jj] = pn[i].y;
            Wns[kq * 4 + 2][jj] = pn[i].z; Wns[kq * 4 + 3][jj] = pn[i].w;
        }
        __syncthreads();
        // prefetch next chunk while computing this one
        int kn = k0 + 32;
        if (kn < nk) {
#pragma unroll
            for (int i = 0; i < 4; i++) {
                int lin = tid + i * 128;
                int bb = lin >> 3, kq = lin & 7;
                pa[i] = __ldcg((const float4*)(A + (size_t)bb * astride + (kn + kq * 4)));
            }
#pragma unroll
            for (int i = 0; i < 2; i++) {
                int lin = tid + i * 128;
                int jj = lin >> 3, kq = lin & 7;
                size_t ro = (size_t)jj * K + (kn + kq * 4);
                pu[i] = *(const float4*)(W + ro);
                pr[i] = *(const float4*)(W + (size_t)HD * K + ro);
                pn[i] = *(const float4*)(W + (size_t)(2 * HD) * K + ro);
            }
        }
#pragma unroll
        for (int kk = 0; kk < 32; kk++) {
            float4 a4 = *(const float4*)&As[kk][ty * 4];
            u64 Ab[4];
            Ab[0] = pack2(a4.x, a4.x); Ab[1] = pack2(a4.y, a4.y);
            Ab[2] = pack2(a4.z, a4.z); Ab[3] = pack2(a4.w, a4.w);
            ulonglong2 wu = *(const ulonglong2*)&Wus[kk][tx * 4];
            ulonglong2 wr = *(const ulonglong2*)&Wrs[kk][tx * 4];
            ulonglong2 wn = *(const ulonglong2*)&Wns[kk][tx * 4];
#pragma unroll
            for (int i = 0; i < 4; i++) {
                ffma2(au[0][i], Ab[i], wu.x); ffma2(au[1][i], Ab[i], wu.y);
                ffma2(ar[0][i], Ab[i], wr.x); ffma2(ar[1][i], Ab[i], wr.y);
                ffma2(an[0][i], Ab[i], wn.x); ffma2(an[1][i], Ab[i], wn.y);
            }
        }
    }
}

// Pred accumulate: 16o x 64b tile, 128 threads, microtile 2o x 4b.
// Accumulators packed over adjacent b (straight ulonglong2 from As, no movs).
__device__ __forceinline__ void accum1(
    const float* __restrict__ A, int astride,
    const float* __restrict__ W, int wstride, int nk,
    u64 (&acc)[2][2],            // [o][bpair]
    int tx, int ty, int tid,
    float (&As)[32][68], float (&Ws)[32][36])
{
    float4 pa[4];
    float4 pw;

#pragma unroll
    for (int i = 0; i < 4; i++) {
        int lin = tid + i * 128;
        int bb = lin >> 3, kq = lin & 7;
        pa[i] = __ldcg((const float4*)(A + (size_t)bb * astride + kq * 4));
    }
    {
        int jj = tid >> 3, kq = tid & 7;   // 16 rows x 8 float4 = 128
        pw = *(const float4*)(W + (size_t)jj * wstride + kq * 4);
    }

    for (int k0 = 0; k0 < nk; k0 += 32) {
        __syncthreads();
#pragma unroll
        for (int i = 0; i < 4; i++) {
            int lin = tid + i * 128;
            int bb = lin >> 3, kq = lin & 7;
            As[kq * 4 + 0][bb] = pa[i].x; As[kq * 4 + 1][bb] = pa[i].y;
            As[kq * 4 + 2][bb] = pa[i].z; As[kq * 4 + 3][bb] = pa[i].w;
        }
        {
            int jj = tid >> 3, kq = tid & 7;
            Ws[kq * 4 + 0][jj] = pw.x; Ws[kq * 4 + 1][jj] = pw.y;
            Ws[kq * 4 + 2][jj] = pw.z; Ws[kq * 4 + 3][jj] = pw.w;
        }
        __syncthreads();
        int kn = k0 + 32;
        if (kn < nk) {
#pragma unroll
            for (int i = 0; i < 4; i++) {
                int lin = tid + i * 128;
                int bb = lin >> 3, kq = lin & 7;
                pa[i] = __ldcg((const float4*)(A + (size_t)bb * astride + (kn + kq * 4)));
            }
            int jj = tid >> 3, kq = tid & 7;
            pw = *(const float4*)(W + (size_t)jj * wstride + (kn + kq * 4));
        }
#pragma unroll
        for (int kk = 0; kk < 32; kk++) {
            ulonglong2 a2 = *(const ulonglong2*)&As[kk][ty * 4];   // (b0,b1),(b2,b3)
            float2 wf = *(const float2*)&Ws[kk][tx * 2];
            u64 W0 = pack2(wf.x, wf.x);
            u64 W1 = pack2(wf.y, wf.y);
            ffma2(acc[0][0], W0, a2.x); ffma2(acc[0][1], W0, a2.y);
            ffma2(acc[1][0], W1, a2.x); ffma2(acc[1][1], W1, a2.y);
        }
    }
}

// ---------------------------------------------------------------------------
// One persistent kernel: entire SGRU sequence + log_softmax + h copy-out.
// grid = 128 blocks, 128 threads.
// ---------------------------------------------------------------------------
__global__ void __launch_bounds__(NTHR) sgru_kernel(
    const float* __restrict__ xb, const float* __restrict__ h0,
    const float* __restrict__ Wx, const float* __restrict__ bx,
    const float* __restrict__ Wh, const float* __restrict__ bh,
    const float* __restrict__ Wo, const float* __restrict__ bo,
    float* __restrict__ out)
{
    __shared__ __align__(16) float As[32][68];
    __shared__ __align__(16) float Wus[32][36];
    __shared__ __align__(16) float Wrs[32][36];
    __shared__ __align__(16) float Wns[32][36];

    int tid = threadIdx.x;
    int bid = blockIdx.x;
    unsigned ls = g_sense;   // read before any block can flip it

    // ---- init: h0 -> g_h[0] ----
    {
        int g = bid * NTHR + tid;
        const float4* s4 = (const float4*)h0;
        float4* d4 = (float4*)g_h[0];
#pragma unroll 1
        for (int i = g; i < B_ * 4 * HD / 4; i += NBLK * NTHR) d4[i] = s4[i];
    }
    grid_barrier(ls);

#pragma unroll 1
    for (int t = 0; t < T_; t++) {
        int rd = t & 1, wr = rd ^ 1;
#pragma unroll 1
        for (int s = 0; s < 4; s++) {
            int wi = (s == 3) ? 2 : s;   // faithful to the source bug

            const float* x;
            int xstride;
            if (s == 0) { x = xb + (size_t)t * INSZ; xstride = T_ * INSZ; }
            else        { x = g_pred[(s - 1) & 1];   xstride = INSZ; }

            // ===== gate phase: 32 j-tiles (32) x 4 b-tiles (64) =====
            {
                int tx = tid & 7, ty = tid >> 3;     // tx: 8 x 4j = 32j, ty: 16 x 4b = 64b
                int j0 = (bid & 31) * 32;
                int b0 = (bid >> 5) * 64;
                const float* Wxp = Wx + (size_t)wi * 3 * HD * INSZ + (size_t)j0 * INSZ;
                const float* Whp = Wh + (size_t)wi * 3 * HD * HD + (size_t)j0 * HD;
                const float* bx3 = bx + wi * 3 * HD;
                const float* bh3 = bh + wi * 3 * HD;
                const float* hrd = g_h[rd] + s * HD;
                float* hwr = g_h[wr] + s * HD;

                u64 au[2][4], ar[2][4], axn[2][4], ahn[2][4];
#pragma unroll
                for (int p = 0; p < 2; p++) {
                    int jg = j0 + tx * 4 + p * 2;
                    u64 bu = pack2(bx3[jg] + bh3[jg], bx3[jg + 1] + bh3[jg + 1]);
                    u64 br = pack2(bx3[HD + jg] + bh3[HD + jg],
                                   bx3[HD + jg + 1] + bh3[HD + jg + 1]);
                    u64 bxn = pack2(bx3[2 * HD + jg], bx3[2 * HD + jg + 1]);
                    u64 bhn = pack2(bh3[2 * HD + jg], bh3[2 * HD + jg + 1]);
#pragma unroll
                    for (int i = 0; i < 4; i++) {
                        au[p][i] = bu; ar[p][i] = br;
                        axn[p][i] = bxn; ahn[p][i] = bhn;
                    }
                }
                accum3(x + (size_t)b0 * xstride, xstride, Wxp, INSZ, INSZ,
                       au, ar, axn, tx, ty, tid, As, Wus, Wrs, Wns);
                accum3(hrd + (size_t)b0 * (4 * HD), 4 * HD, Whp, HD, HD,
                       au, ar, ahn, tx, ty, tid, As, Wus, Wrs, Wns);

#pragma unroll
                for (int i = 0; i < 4; i++) {
                    int b = b0 + ty * 4 + i;
                    int jg = j0 + tx * 4;
                    float4 hold = __ldcg((const float4*)(hrd + (size_t)b * (4 * HD) + jg));
                    float ho[4] = {hold.x, hold.y, hold.z, hold.w};
                    float uv[4], rv[4], xnv[4], hnv[4];
#pragma unroll
                    for (int p = 0; p < 2; p++) {
                        unpack2(au[p][i], uv[p * 2], uv[p * 2 + 1]);
                        unpack2(ar[p][i], rv[p * 2], rv[p * 2 + 1]);
                        unpack2(axn[p][i], xnv[p * 2], xnv[p * 2 + 1]);
                        unpack2(ahn[p][i], hnv[p * 2], hnv[p * 2 + 1]);
                    }
                    float4 hv;
                    float* hvp = &hv.x;
#pragma unroll
                    for (int jj = 0; jj < 4; jj++) {
                        float u = 1.0f / (1.0f + expf(-uv[jj]));
                        float r = 1.0f / (1.0f + expf(-rv[jj]));
                        float n = tanhf(xnv[jj] + r * hnv[jj]);
                        hvp[jj] = u * ho[jj] + (1.0f - u) * n;
                    }
                    *(float4*)(hwr + (size_t)b * (4 * HD) + jg) = hv;
                }
            }
            grid_barrier(ls);

            // ===== pred phase: 32 o-tiles (16) x 4 b-tiles (64) =====
            {
                int tx = tid & 7, ty = tid >> 3;     // tx: 8 x 2o = 16o, ty: 16 x 4b = 64b
                int o0 = (bid & 31) * 16;
                int b0 = (bid >> 5) * 64;
                const float* Wop = Wo + (size_t)wi * INSZ * (HD + INSZ) + (size_t)o0 * (HD + INSZ);
                const float* bop = bo + wi * INSZ;
                const float* hn = g_h[wr] + s * HD;

                u64 acc[2][2];   // [o][bpair]
                acc[0][0] = acc[0][1] = pack2(bop[o0 + tx * 2], bop[o0 + tx * 2]);
                acc[1][0] = acc[1][1] = pack2(bop[o0 + tx * 2 + 1], bop[o0 + tx * 2 + 1]);

                accum1(x + (size_t)b0 * xstride, xstride,
                       Wop, HD + INSZ, INSZ, acc, tx, ty, tid, As, Wus);
                accum1(hn + (size_t)b0 * (4 * HD), 4 * HD,
                       Wop + INSZ, HD + INSZ, HD, acc, tx, ty, tid, As, Wus);

                float* outp; int ostr;
                if (s == 3) { outp = out + (size_t)t * INSZ; ostr = T_ * INSZ; }
                else        { outp = g_pred[s & 1];          ostr = INSZ; }

                float o0b[4], o1b[4];
                unpack2(acc[0][0], o0b[0], o0b[1]); unpack2(acc[0][1], o0b[2], o0b[3]);
                unpack2(acc[1][0], o1b[0], o1b[1]); unpack2(acc[1][1], o1b[2], o1b[3]);
#pragma unroll
                for (int i = 0; i < 4; i++) {
                    int b = b0 + ty * 4 + i;
                    float2 v = make_float2(o0b[i], o1b[i]);
                    *(float2*)(outp + (size_t)b * ostr + (o0 + tx * 2)) = v;
                }
            }
            grid_barrier(ls);
        }
    }

    // ---- copy final h (in g_h[0]) to out tail ----
    {
        int g = bid * NTHR + tid;
        const float4* s4 = (const float4*)g_h[0];
        float4* d4 = (float4*)(out + (size_t)B_ * T_ * INSZ);
#pragma unroll 1
        for (int i = g; i < B_ * 4 * HD / 4; i += NBLK * NTHR) d4[i] = __ldcg(s4 + i);
    }

    // ---- log_softmax over each 512-wide pred row ----
    {
        int w = tid >> 5, ln = tid & 31;      // 4 warps per block
        int gw = bid * 4 + w;
#pragma unroll 1
        for (int r = gw; r < B_ * T_; r += NBLK * 4) {
            float* p = out + (size_t)r * INSZ;
            float v[16];
            float m = -1e30f;
#pragma unroll
            for (int i = 0; i < 16; i++) {
                v[i] = __ldcg(p + ln + i * 32);
                m = fmaxf(m, v[i]);
            }
#pragma unroll
            for (int off = 16; off > 0; off >>= 1)
                m = fmaxf(m, __shfl_xor_sync(0xffffffffu, m, off));
            float sm = 0.0f;
#pragma unroll
            for (int i = 0; i < 16; i++) sm += expf(v[i] - m);
#pragma unroll
            for (int off = 16; off > 0; off >>= 1)
                sm += __shfl_xor_sync(0xffffffffu, sm, off);
            float lsv = m + logf(sm);
#pragma unroll
            for (int i = 0; i < 16; i++) p[ln + i * 32] = v[i] - lsv;
        }
    }
}

// ---------------------------------------------------------------------------
extern "C" void kernel_launch(void* const* d_in, const int* in_sizes, int n_in,
                              void* d_out, int out_size)
{
    const float* xb = (const float*)d_in[0];
    const float* h0 = (const float*)d_in[1];
    const float* Wx = (const float*)d_in[2];
    const float* bx = (const float*)d_in[3];
    const float* Wh = (const float*)d_in[4];
    const float* bh = (const float*)d_in[5];
    const float* Wo = (const float*)d_in[6];
    const float* bo = (const float*)d_in[7];
    float* out = (float*)d_out;

    sgru_kernel<<<NBLK, NTHR>>>(xb, h0, Wx, bx, Wh, bh, Wo, bo, out);
}